// round 15
// baseline (speedup 1.0000x reference)
#include <cuda_runtime.h>
#include <cuda_bf16.h>
#include <cstdint>
#include <cstddef>

#define NNODES 100000
#define NEDGES 1600000
#define MAXF   256

// ---------------- scratch (device globals; no allocations allowed) ----------
__device__ float g_h[(size_t)NNODES * MAXF];          // h = X @ W (fp32)
__device__ __align__(16) __nv_bfloat16 g_feat_hi[(size_t)NNODES * MAXF];
__device__ __align__(16) __nv_bfloat16 g_feat_lo[(size_t)NNODES * MAXF];
__device__ __align__(16) __nv_bfloat16 g_wt_hi[256 * 256];  // W^T split hi [n][k]
__device__ __align__(16) __nv_bfloat16 g_wt_lo[256 * 256];  // W^T split lo [n][k]
__device__ float g_als[(size_t)NNODES * 4];
__device__ float g_ald[(size_t)NNODES * 4];

// CSR-by-dst build scratch
__device__ int g_csr_src[NEDGES];
__device__ int g_deg[NNODES];
__device__ int g_rowptr[NNODES + 1];
__device__ int g_cursor[NNODES];

// ---------------- helpers ----------------------------------------------------
__device__ __forceinline__ void split_bf16(float v, __nv_bfloat16& hi, __nv_bfloat16& lo) {
    hi = __float2bfloat16(v);
    lo = __float2bfloat16(v - __bfloat162float(hi));
}
__device__ __forceinline__ void mma_bf16(float* c, const uint32_t* a, const uint32_t* b) {
    asm volatile(
        "mma.sync.aligned.m16n8k16.row.col.f32.bf16.bf16.f32 "
        "{%0,%1,%2,%3}, {%4,%5,%6,%7}, {%8,%9}, {%0,%1,%2,%3};"
        : "+f"(c[0]), "+f"(c[1]), "+f"(c[2]), "+f"(c[3])
        : "r"(a[0]), "r"(a[1]), "r"(a[2]), "r"(a[3]), "r"(b[0]), "r"(b[1]));
}
__device__ __forceinline__ void ldsm_x4(uint32_t& r0, uint32_t& r1, uint32_t& r2,
                                        uint32_t& r3, uint32_t addr) {
    asm volatile("ldmatrix.sync.aligned.m8n8.x4.shared.b16 {%0,%1,%2,%3}, [%4];"
                 : "=r"(r0), "=r"(r1), "=r"(r2), "=r"(r3) : "r"(addr));
}

// ---------------- operand split kernels --------------------------------------
__global__ void splitx(const float* __restrict__ x, __nv_bfloat16* __restrict__ xhi,
                       __nv_bfloat16* __restrict__ xlo, int total4) {
    int i = blockIdx.x * blockDim.x + threadIdx.x;
    if (i >= total4) return;
    float4 v = ((const float4*)x)[i];
    __nv_bfloat16 h[4], l[4];
    split_bf16(v.x, h[0], l[0]); split_bf16(v.y, h[1], l[1]);
    split_bf16(v.z, h[2], l[2]); split_bf16(v.w, h[3], l[3]);
    *(uint2*)&xhi[(size_t)i * 4] = *(uint2*)h;
    *(uint2*)&xlo[(size_t)i * 4] = *(uint2*)l;
}
__global__ void wsplit(const float* __restrict__ W, __nv_bfloat16* __restrict__ wthi,
                       __nv_bfloat16* __restrict__ wtlo, int K, int F) {
    int i = blockIdx.x * blockDim.x + threadIdx.x;
    if (i >= K * F) return;
    int k = i / F, n = i % F;
    __nv_bfloat16 h, l;
    split_bf16(W[i], h, l);
    wthi[n * K + k] = h;
    wtlo[n * K + k] = l;
}

// ---------------- GEMM: C[M,Nc] = A[M,K] @ B[K,Nc] via bf16x3 + ldmatrix -----
// Block 128x64, BK=16, double-buffered, 256 threads = 8 warps (4M x 2N),
// warp tile 32x32 = 2 m16 x 4 n8, mma m16n8k16. Products: hi*hi + hi*lo + lo*hi.
#define GBM 128
#define GBN 64
#define GBK 16
#define SSTR 24    // bf16 row stride: 48B rows, 16B-aligned, 12r mod 32 permutes

__global__ __launch_bounds__(256) void gemm_bf16x3(
    const __nv_bfloat16* __restrict__ Ahi, const __nv_bfloat16* __restrict__ Alo,
    const __nv_bfloat16* __restrict__ Bhi, const __nv_bfloat16* __restrict__ Blo,
    float* __restrict__ C, int M, int K, int Nc) {
    __shared__ __align__(16) __nv_bfloat16 sA[2][2][GBM][SSTR];  // [buf][hi/lo]
    __shared__ __align__(16) __nv_bfloat16 sB[2][2][GBN][SSTR];
    const int tid = threadIdx.x;
    const int warp = tid >> 5, lane = tid & 31;
    const int wm = warp >> 1, wn = warp & 1;
    const int g = lane >> 2, t4 = lane & 3;
    const int l8 = lane & 7, g8 = lane >> 3;
    const int row0 = blockIdx.y * GBM, col0 = blockIdx.x * GBN;
    const int KT = K / GBK;

    const uint32_t sA0 = (uint32_t)__cvta_generic_to_shared(&sA[0][0][0][0]);
    const uint32_t sB0 = (uint32_t)__cvta_generic_to_shared(&sB[0][0][0][0]);

    const int a_r = l8 + ((g8 & 1) << 3);
    const int a_c = (g8 >> 1) << 3;
    const int b_n = l8 + ((g8 >> 1) << 3);
    const int b_c = (g8 & 1) << 3;

    const int ra = tid >> 1, kh = (tid & 1) * 8;
    const int rb = tid >> 2, kb = (tid & 3) * 4;

    uint4 vAh, vAl;
    uint2 vBh, vBl;

#define GLDG(ktv)                                                                  \
    do {                                                                           \
        int k0_ = (ktv) * GBK;                                                     \
        int gr_ = row0 + ra;                                                       \
        if (gr_ < M) {                                                             \
            vAh = *(const uint4*)&Ahi[(size_t)gr_ * K + k0_ + kh];                 \
            vAl = *(const uint4*)&Alo[(size_t)gr_ * K + k0_ + kh];                 \
        } else {                                                                   \
            vAh = make_uint4(0, 0, 0, 0); vAl = make_uint4(0, 0, 0, 0);            \
        }                                                                          \
        vBh = *(const uint2*)&Bhi[(size_t)(col0 + rb) * K + k0_ + kb];             \
        vBl = *(const uint2*)&Blo[(size_t)(col0 + rb) * K + k0_ + kb];             \
    } while (0)

#define GSTS(buf)                                                                  \
    do {                                                                           \
        *(uint4*)&sA[buf][0][ra][kh] = vAh;                                        \
        *(uint4*)&sA[buf][1][ra][kh] = vAl;                                        \
        *(uint2*)&sB[buf][0][rb][kb] = vBh;                                        \
        *(uint2*)&sB[buf][1][rb][kb] = vBl;                                        \
    } while (0)

    float acc[2][4][4];
#pragma unroll
    for (int mt = 0; mt < 2; mt++)
#pragma unroll
        for (int nt = 0; nt < 4; nt++)
#pragma unroll
            for (int i = 0; i < 4; i++) acc[mt][nt][i] = 0.0f;

    GLDG(0); GSTS(0);
    if (KT > 1) GLDG(1);
    __syncthreads();

    for (int kt = 0; kt < KT; kt++) {
        int buf = kt & 1;
        uint32_t ah[2][4], al_[2][4], bh[4][2], bl[4][2];
#pragma unroll
        for (int mt = 0; mt < 2; mt++) {
            int r = wm * 32 + mt * 16 + a_r;
            uint32_t oh = sA0 + (uint32_t)((((buf * 2 + 0) * GBM + r) * SSTR + a_c) * 2);
            uint32_t ol = sA0 + (uint32_t)((((buf * 2 + 1) * GBM + r) * SSTR + a_c) * 2);
            ldsm_x4(ah[mt][0], ah[mt][1], ah[mt][2], ah[mt][3], oh);
            ldsm_x4(al_[mt][0], al_[mt][1], al_[mt][2], al_[mt][3], ol);
        }
#pragma unroll
        for (int p = 0; p < 2; p++) {
            int n = wn * 32 + p * 16 + b_n;
            uint32_t oh = sB0 + (uint32_t)((((buf * 2 + 0) * GBN + n) * SSTR + b_c) * 2);
            uint32_t ol = sB0 + (uint32_t)((((buf * 2 + 1) * GBN + n) * SSTR + b_c) * 2);
            ldsm_x4(bh[2 * p][0], bh[2 * p][1], bh[2 * p + 1][0], bh[2 * p + 1][1], oh);
            ldsm_x4(bl[2 * p][0], bl[2 * p][1], bl[2 * p + 1][0], bl[2 * p + 1][1], ol);
        }
#pragma unroll
        for (int mt = 0; mt < 2; mt++)
#pragma unroll
            for (int nt = 0; nt < 4; nt++) {
                mma_bf16(acc[mt][nt], ah[mt], bh[nt]);   // hi*hi
                mma_bf16(acc[mt][nt], ah[mt], bl[nt]);   // hi*lo
                mma_bf16(acc[mt][nt], al_[mt], bh[nt]);  // lo*hi
            }
        if (kt + 1 < KT) GSTS((kt + 1) & 1);
        if (kt + 2 < KT) GLDG(kt + 2);
        __syncthreads();
    }

#pragma unroll
    for (int mt = 0; mt < 2; mt++) {
        int rbm = row0 + wm * 32 + mt * 16 + g;
#pragma unroll
        for (int nt = 0; nt < 4; nt++) {
            int cc = col0 + wn * 32 + nt * 8 + t4 * 2;
            if (rbm < M)
                *(float2*)&C[(size_t)rbm * Nc + cc] =
                    make_float2(acc[mt][nt][0], acc[mt][nt][1]);
            if (rbm + 8 < M)
                *(float2*)&C[(size_t)(rbm + 8) * Nc + cc] =
                    make_float2(acc[mt][nt][2], acc[mt][nt][3]);
        }
    }
#undef GLDG
#undef GSTS
}

// ---------------- per-node attention logits ---------------------------------
__global__ void al_kernel(const float* __restrict__ h,
                          const float* __restrict__ asrc,
                          const float* __restrict__ adst,
                          float* __restrict__ al_s, float* __restrict__ al_d,
                          int H, int C) {
    int n = blockIdx.x;
    int head = threadIdx.x >> 5;
    int lane = threadIdx.x & 31;
    const float* hp = h + (size_t)n * H * C + head * C;
    float ss = 0.0f, sd = 0.0f;
    for (int c = lane; c < C; c += 32) {
        float v = hp[c];
        ss += v * asrc[head * C + c];
        sd += v * adst[head * C + c];
    }
#pragma unroll
    for (int o = 16; o; o >>= 1) {
        ss += __shfl_xor_sync(0xFFFFFFFFu, ss, o);
        sd += __shfl_xor_sync(0xFFFFFFFFu, sd, o);
    }
    if (lane == 0) {
        al_s[n * H + head] = ss;
        al_d[n * H + head] = sd;
    }
}

// ---------------- CSR build ------------------------------------------------
__global__ void zero_deg(int* __restrict__ deg, int N) {
    int i = blockIdx.x * blockDim.x + threadIdx.x;
    if (i < N) deg[i] = 0;
}
__global__ void build_deg(const int* __restrict__ dst, int* __restrict__ deg, int E) {
    int e = blockIdx.x * blockDim.x + threadIdx.x;
    if (e < E) atomicAdd(&deg[dst[e]], 1);
}
__global__ void scan_full(const int* __restrict__ deg, int* __restrict__ rowptr,
                          int* __restrict__ cursor, int n, int E) {
    __shared__ int wsum[32];
    __shared__ int carry;
    int lane = threadIdx.x & 31, wid = threadIdx.x >> 5;
    if (threadIdx.x == 0) carry = 0;
    __syncthreads();
    for (int base = 0; base < n; base += 1024) {
        int gid = base + threadIdx.x;
        int v = (gid < n) ? deg[gid] : 0;
        int x = v;
#pragma unroll
        for (int off = 1; off < 32; off <<= 1) {
            int y = __shfl_up_sync(0xFFFFFFFFu, x, off);
            if (lane >= off) x += y;
        }
        if (lane == 31) wsum[wid] = x;
        __syncthreads();
        if (wid == 0) {
            int w = wsum[lane];
#pragma unroll
            for (int off = 1; off < 32; off <<= 1) {
                int y = __shfl_up_sync(0xFFFFFFFFu, w, off);
                if (lane >= off) w += y;
            }
            wsum[lane] = w;
        }
        __syncthreads();
        int incl = x + ((wid > 0) ? wsum[wid - 1] : 0) + carry;
        if (gid < n) {
            rowptr[gid] = incl - v;
            cursor[gid] = incl - v;
        }
        __syncthreads();
        if (threadIdx.x == 1023) carry = incl;
        __syncthreads();
    }
    if (threadIdx.x == 0) rowptr[n] = E;
}
__global__ void scatter(const int* __restrict__ src, const int* __restrict__ dst,
                        int* __restrict__ cursor, int* __restrict__ csr_src, int E) {
    int e = blockIdx.x * blockDim.x + threadIdx.x;
    if (e >= E) return;
    int pos = atomicAdd(&cursor[dst[e]], 1);
    csr_src[pos] = src[e];
}

// ---------------- head-sliced GAT: one warp per (node, head), H=4 -----------
// Warps grouped by head (gw/N = head) so each execution phase touches only one
// head's ~25MB h-slice -> L2-resident gather. Writes bf16 hi/lo feat + ELU.
__global__ void node_gat4(const int* __restrict__ rowptr,
                          const int* __restrict__ csr_src,
                          const float* __restrict__ als,
                          const float* __restrict__ ald,
                          const float* __restrict__ h,
                          const float* __restrict__ bias,
                          __nv_bfloat16* __restrict__ fhi,
                          __nv_bfloat16* __restrict__ flo, int N) {
    int gw = (blockIdx.x * blockDim.x + threadIdx.x) >> 5;
    int lane = threadIdx.x & 31;
    if (gw >= 4 * N) return;
    const int k = gw / N;          // head
    const int d = gw - k * N;      // node
    const int beg = rowptr[d], end = rowptr[d + 1];
    const float aldv = ald[d * 4 + k];

    // online softmax for this head
    float m = -3.402823466e38f, sum = 0.0f;
    for (int i = beg + lane; i < end; i += 32) {
        int s = csr_src[i];
        float v = als[s * 4 + k] + aldv;
        v = (v >= 0.0f) ? v : 0.2f * v;
        if (v <= m) {
            sum += __expf(v - m);
        } else {
            sum = sum * __expf(m - v) + 1.0f;
            m = v;
        }
    }
#pragma unroll
    for (int o = 16; o; o >>= 1) {
        float om = __shfl_xor_sync(0xFFFFFFFFu, m, o);
        float os = __shfl_xor_sync(0xFFFFFFFFu, sum, o);
        float nm = fmaxf(m, om);
        sum = sum * __expf(m - nm) + os * __expf(om - nm);
        m = nm;
    }
    float inv = 1.0f / (sum + 1e-16f);

    // aggregate this head's 64-float slice (coalesced 256B per edge)
    float2 acc = make_float2(0.f, 0.f);
#pragma unroll 2
    for (int i = beg; i < end; i++) {
        int s = csr_src[i];
        float v = als[s * 4 + k] + aldv;
        v = (v >= 0.0f) ? v : 0.2f * v;
        float w = __expf(v - m) * inv;
        float2 hv = ((const float2*)(h + (size_t)s * 256 + k * 64))[lane];
        acc.x += w * hv.x;
        acc.y += w * hv.y;
    }
    int c = k * 64 + lane * 2;
    float o0 = acc.x + bias[c];
    float o1 = acc.y + bias[c + 1];
    o0 = (o0 > 0.f) ? o0 : expm1f(o0);
    o1 = (o1 > 0.f) ? o1 : expm1f(o1);
    __nv_bfloat16 h2[2], l2[2];
    split_bf16(o0, h2[0], l2[0]);
    split_bf16(o1, h2[1], l2[1]);
    *(uint32_t*)&fhi[(size_t)d * 256 + c] = *(uint32_t*)h2;
    *(uint32_t*)&flo[(size_t)d * 256 + c] = *(uint32_t*)l2;
}

// ---------------- final layer: one warp per node, H=1, C=64, fp32 out -------
__global__ void node_gat1(const int* __restrict__ rowptr,
                          const int* __restrict__ csr_src,
                          const float* __restrict__ als,
                          const float* __restrict__ ald,
                          const float* __restrict__ h,
                          const float* __restrict__ bias,
                          float* __restrict__ out, int N) {
    int d = (blockIdx.x * blockDim.x + threadIdx.x) >> 5;
    int lane = threadIdx.x & 31;
    if (d >= N) return;
    const int beg = rowptr[d], end = rowptr[d + 1];
    const float aldv = ald[d];

    float m = -3.402823466e38f, sum = 0.0f;
    for (int i = beg + lane; i < end; i += 32) {
        int s = csr_src[i];
        float v = als[s] + aldv;
        v = (v >= 0.0f) ? v : 0.2f * v;
        if (v <= m) {
            sum += __expf(v - m);
        } else {
            sum = sum * __expf(m - v) + 1.0f;
            m = v;
        }
    }
#pragma unroll
    for (int o = 16; o; o >>= 1) {
        float om = __shfl_xor_sync(0xFFFFFFFFu, m, o);
        float os = __shfl_xor_sync(0xFFFFFFFFu, sum, o);
        float nm = fmaxf(m, om);
        sum = sum * __expf(m - nm) + os * __expf(om - nm);
        m = nm;
    }
    float inv = 1.0f / (sum + 1e-16f);

    float2 acc = make_float2(0.f, 0.f);
#pragma unroll 2
    for (int i = beg; i < end; i++) {
        int s = csr_src[i];
        float v = als[s] + aldv;
        v = (v >= 0.0f) ? v : 0.2f * v;
        float w = __expf(v - m) * inv;
        float2 hv = ((const float2*)(h + (size_t)s * 64))[lane];
        acc.x += w * hv.x;
        acc.y += w * hv.y;
    }
    int c = lane * 2;
    acc.x += bias[c];
    acc.y += bias[c + 1];
    *(float2*)&out[(size_t)d * 64 + c] = acc;
}

// ---------------- launch ----------------------------------------------------
extern "C" void kernel_launch(void* const* d_in, const int* in_sizes, int n_in,
                              void* d_out, int out_size) {
    const float* x = (const float*)d_in[0];
    const int* ei = (const int*)d_in[1];   // int32 (JAX x64-disabled)
    const int N = in_sizes[0] / 128;
    const int E = in_sizes[1] / 2;
    const int* src = ei;
    const int* dst = ei + E;

    float *h, *als, *ald;
    __nv_bfloat16 *fhi, *flo, *wthi, *wtlo;
    int *csr_src, *deg, *rowptr, *cursor;
    cudaGetSymbolAddress((void**)&h,       g_h);
    cudaGetSymbolAddress((void**)&fhi,     g_feat_hi);
    cudaGetSymbolAddress((void**)&flo,     g_feat_lo);
    cudaGetSymbolAddress((void**)&wthi,    g_wt_hi);
    cudaGetSymbolAddress((void**)&wtlo,    g_wt_lo);
    cudaGetSymbolAddress((void**)&als,     g_als);
    cudaGetSymbolAddress((void**)&ald,     g_ald);
    cudaGetSymbolAddress((void**)&csr_src, g_csr_src);
    cudaGetSymbolAddress((void**)&deg,     g_deg);
    cudaGetSymbolAddress((void**)&rowptr,  g_rowptr);
    cudaGetSymbolAddress((void**)&cursor,  g_cursor);

    const float* W[4]   = {(const float*)d_in[3],  (const float*)d_in[7],
                           (const float*)d_in[11], (const float*)d_in[15]};
    const float* Asr[4] = {(const float*)d_in[4],  (const float*)d_in[8],
                           (const float*)d_in[12], (const float*)d_in[16]};
    const float* Ads[4] = {(const float*)d_in[5],  (const float*)d_in[9],
                           (const float*)d_in[13], (const float*)d_in[17]};
    const float* Bb[4]  = {(const float*)d_in[6],  (const float*)d_in[10],
                           (const float*)d_in[14], (const float*)d_in[18]};
    const int Ci[4] = {128, 256, 256, 256};
    const int Hh[4] = {4, 4, 4, 1};

    // Prologue ordered so launch index 3 is the layer-0 gemm (ncu samples it).
    wsplit<<<(Ci[0] * 256 + 255) / 256, 256>>>(W[0], wthi, wtlo, Ci[0], 256);     // 0
    splitx<<<(N * 32 + 255) / 256, 256>>>(x, fhi, flo, N * 32);                   // 1
    zero_deg<<<(N + 255) / 256, 256>>>(deg, N);                                   // 2

    for (int l = 0; l < 4; l++) {
        const int H = Hh[l], C = 64, F = H * 64, K = Ci[l];

        dim3 ggrid(F / GBN, (N + GBM - 1) / GBM);
        gemm_bf16x3<<<ggrid, 256>>>(fhi, flo, wthi, wtlo, h, N, K, F);            // 3 (l=0)

        al_kernel<<<N, 32 * H>>>(h, Asr[l], Ads[l], als, ald, H, C);

        if (l == 0) {
            build_deg<<<(E + 255) / 256, 256>>>(dst, deg, E);
            scan_full<<<1, 1024>>>(deg, rowptr, cursor, N, E);
            scatter<<<(E + 255) / 256, 256>>>(src, dst, cursor, csr_src, E);
        }

        if (l < 3) {
            int ngrid = (N * 4 + 7) / 8;   // 4N warps, 8 warps/block
            node_gat4<<<ngrid, 256>>>(rowptr, csr_src, als, ald, h, Bb[l],
                                      fhi, flo, N);
            wsplit<<<(Ci[l + 1] * ((l + 1 < 3) ? 256 : 64) + 255) / 256, 256>>>(
                W[l + 1], wthi, wtlo, Ci[l + 1], (l + 1 < 3) ? 256 : 64);
        } else {
            int ngrid = (N + 7) / 8;
            node_gat1<<<ngrid, 256>>>(rowptr, csr_src, als, ald, h, Bb[l],
                                      (float*)d_out, N);
        }
    }
}

// round 16
// speedup vs baseline: 1.1648x; 1.1648x over previous
#include <cuda_runtime.h>
#include <cuda_bf16.h>
#include <cstdint>
#include <cstddef>

#define NNODES 100000
#define NEDGES 1600000
#define MAXF   256

// ---------------- scratch (device globals; no allocations allowed) ----------
__device__ float g_h[(size_t)NNODES * MAXF];          // h = X @ W (fp32)
__device__ __align__(16) __nv_bfloat16 g_feat_hi[(size_t)NNODES * MAXF];
__device__ __align__(16) __nv_bfloat16 g_feat_lo[(size_t)NNODES * MAXF];
__device__ __align__(16) __nv_bfloat16 g_wt_hi[256 * 256];  // W^T split hi [n][k]
__device__ __align__(16) __nv_bfloat16 g_wt_lo[256 * 256];  // W^T split lo [n][k]
__device__ float g_als[(size_t)NNODES * 4];
__device__ float g_ald[(size_t)NNODES * 4];

// CSR-by-dst build scratch
__device__ int g_csr_src[NEDGES];
__device__ int g_deg[NNODES];
__device__ int g_rowptr[NNODES + 1];
__device__ int g_cursor[NNODES];

// ---------------- helpers ----------------------------------------------------
__device__ __forceinline__ void split_bf16(float v, __nv_bfloat16& hi, __nv_bfloat16& lo) {
    hi = __float2bfloat16(v);
    lo = __float2bfloat16(v - __bfloat162float(hi));
}
__device__ __forceinline__ void mma_bf16(float* c, const uint32_t* a, const uint32_t* b) {
    asm volatile(
        "mma.sync.aligned.m16n8k16.row.col.f32.bf16.bf16.f32 "
        "{%0,%1,%2,%3}, {%4,%5,%6,%7}, {%8,%9}, {%0,%1,%2,%3};"
        : "+f"(c[0]), "+f"(c[1]), "+f"(c[2]), "+f"(c[3])
        : "r"(a[0]), "r"(a[1]), "r"(a[2]), "r"(a[3]), "r"(b[0]), "r"(b[1]));
}
__device__ __forceinline__ void ldsm_x4(uint32_t& r0, uint32_t& r1, uint32_t& r2,
                                        uint32_t& r3, uint32_t addr) {
    asm volatile("ldmatrix.sync.aligned.m8n8.x4.shared.b16 {%0,%1,%2,%3}, [%4];"
                 : "=r"(r0), "=r"(r1), "=r"(r2), "=r"(r3) : "r"(addr));
}

// ---------------- operand split kernels --------------------------------------
__global__ void splitx(const float* __restrict__ x, __nv_bfloat16* __restrict__ xhi,
                       __nv_bfloat16* __restrict__ xlo, int total4) {
    int i = blockIdx.x * blockDim.x + threadIdx.x;
    if (i >= total4) return;
    float4 v = ((const float4*)x)[i];
    __nv_bfloat16 h[4], l[4];
    split_bf16(v.x, h[0], l[0]); split_bf16(v.y, h[1], l[1]);
    split_bf16(v.z, h[2], l[2]); split_bf16(v.w, h[3], l[3]);
    *(uint2*)&xhi[(size_t)i * 4] = *(uint2*)h;
    *(uint2*)&xlo[(size_t)i * 4] = *(uint2*)l;
}
__global__ void wsplit(const float* __restrict__ W, __nv_bfloat16* __restrict__ wthi,
                       __nv_bfloat16* __restrict__ wtlo, int K, int F) {
    int i = blockIdx.x * blockDim.x + threadIdx.x;
    if (i >= K * F) return;
    int k = i / F, n = i % F;
    __nv_bfloat16 h, l;
    split_bf16(W[i], h, l);
    wthi[n * K + k] = h;
    wtlo[n * K + k] = l;
}
__global__ void zal(float* __restrict__ als, float* __restrict__ ald, int n) {
    int i = blockIdx.x * blockDim.x + threadIdx.x;
    if (i < n) { als[i] = 0.0f; ald[i] = 0.0f; }
}

// ---------------- GEMM: C[M,Nc] = A[M,K] @ B[K,Nc] via bf16x3 + ldmatrix -----
// Block 128x64, BK=16, double-buffered, 256 threads = 8 warps (4M x 2N),
// warp tile 32x32. FUSED epilogue: attention logit partials -> atomicAdd als/ald
// (each block covers exactly one head: GBN == C == 64).
#define GBM 128
#define GBN 64
#define GBK 16
#define SSTR 24    // bf16 row stride: 48B rows, 16B-aligned, 12r mod 32 permutes

__global__ __launch_bounds__(256) void gemm_bf16x3(
    const __nv_bfloat16* __restrict__ Ahi, const __nv_bfloat16* __restrict__ Alo,
    const __nv_bfloat16* __restrict__ Bhi, const __nv_bfloat16* __restrict__ Blo,
    float* __restrict__ C, int M, int K, int Nc,
    const float* __restrict__ asrc, const float* __restrict__ adst,
    float* __restrict__ als, float* __restrict__ ald, int Hn) {
    __shared__ __align__(16) __nv_bfloat16 sA[2][2][GBM][SSTR];  // [buf][hi/lo]
    __shared__ __align__(16) __nv_bfloat16 sB[2][2][GBN][SSTR];
    const int tid = threadIdx.x;
    const int warp = tid >> 5, lane = tid & 31;
    const int wm = warp >> 1, wn = warp & 1;
    const int g = lane >> 2, t4 = lane & 3;
    const int l8 = lane & 7, g8 = lane >> 3;
    const int row0 = blockIdx.y * GBM, col0 = blockIdx.x * GBN;
    const int KT = K / GBK;

    const uint32_t sA0 = (uint32_t)__cvta_generic_to_shared(&sA[0][0][0][0]);
    const uint32_t sB0 = (uint32_t)__cvta_generic_to_shared(&sB[0][0][0][0]);

    const int a_r = l8 + ((g8 & 1) << 3);
    const int a_c = (g8 >> 1) << 3;
    const int b_n = l8 + ((g8 >> 1) << 3);
    const int b_c = (g8 & 1) << 3;

    const int ra = tid >> 1, kh = (tid & 1) * 8;
    const int rb = tid >> 2, kb = (tid & 3) * 4;

    uint4 vAh, vAl;
    uint2 vBh, vBl;

#define GLDG(ktv)                                                                  \
    do {                                                                           \
        int k0_ = (ktv) * GBK;                                                     \
        int gr_ = row0 + ra;                                                       \
        if (gr_ < M) {                                                             \
            vAh = *(const uint4*)&Ahi[(size_t)gr_ * K + k0_ + kh];                 \
            vAl = *(const uint4*)&Alo[(size_t)gr_ * K + k0_ + kh];                 \
        } else {                                                                   \
            vAh = make_uint4(0, 0, 0, 0); vAl = make_uint4(0, 0, 0, 0);            \
        }                                                                          \
        vBh = *(const uint2*)&Bhi[(size_t)(col0 + rb) * K + k0_ + kb];             \
        vBl = *(const uint2*)&Blo[(size_t)(col0 + rb) * K + k0_ + kb];             \
    } while (0)

#define GSTS(buf)                                                                  \
    do {                                                                           \
        *(uint4*)&sA[buf][0][ra][kh] = vAh;                                        \
        *(uint4*)&sA[buf][1][ra][kh] = vAl;                                        \
        *(uint2*)&sB[buf][0][rb][kb] = vBh;                                        \
        *(uint2*)&sB[buf][1][rb][kb] = vBl;                                        \
    } while (0)

    float acc[2][4][4];
#pragma unroll
    for (int mt = 0; mt < 2; mt++)
#pragma unroll
        for (int nt = 0; nt < 4; nt++)
#pragma unroll
            for (int i = 0; i < 4; i++) acc[mt][nt][i] = 0.0f;

    GLDG(0); GSTS(0);
    if (KT > 1) GLDG(1);
    __syncthreads();

    for (int kt = 0; kt < KT; kt++) {
        int buf = kt & 1;
        uint32_t ah[2][4], al_[2][4], bh[4][2], bl[4][2];
#pragma unroll
        for (int mt = 0; mt < 2; mt++) {
            int r = wm * 32 + mt * 16 + a_r;
            uint32_t oh = sA0 + (uint32_t)((((buf * 2 + 0) * GBM + r) * SSTR + a_c) * 2);
            uint32_t ol = sA0 + (uint32_t)((((buf * 2 + 1) * GBM + r) * SSTR + a_c) * 2);
            ldsm_x4(ah[mt][0], ah[mt][1], ah[mt][2], ah[mt][3], oh);
            ldsm_x4(al_[mt][0], al_[mt][1], al_[mt][2], al_[mt][3], ol);
        }
#pragma unroll
        for (int p = 0; p < 2; p++) {
            int n = wn * 32 + p * 16 + b_n;
            uint32_t oh = sB0 + (uint32_t)((((buf * 2 + 0) * GBN + n) * SSTR + b_c) * 2);
            uint32_t ol = sB0 + (uint32_t)((((buf * 2 + 1) * GBN + n) * SSTR + b_c) * 2);
            ldsm_x4(bh[2 * p][0], bh[2 * p][1], bh[2 * p + 1][0], bh[2 * p + 1][1], oh);
            ldsm_x4(bl[2 * p][0], bl[2 * p][1], bl[2 * p + 1][0], bl[2 * p + 1][1], ol);
        }
#pragma unroll
        for (int mt = 0; mt < 2; mt++)
#pragma unroll
            for (int nt = 0; nt < 4; nt++) {
                mma_bf16(acc[mt][nt], ah[mt], bh[nt]);   // hi*hi
                mma_bf16(acc[mt][nt], ah[mt], bl[nt]);   // hi*lo
                mma_bf16(acc[mt][nt], al_[mt], bh[nt]);  // lo*hi
            }
        if (kt + 1 < KT) GSTS((kt + 1) & 1);
        if (kt + 2 < KT) GLDG(kt + 2);
        __syncthreads();
    }

    // store C
#pragma unroll
    for (int mt = 0; mt < 2; mt++) {
        int rbm = row0 + wm * 32 + mt * 16 + g;
#pragma unroll
        for (int nt = 0; nt < 4; nt++) {
            int cc = col0 + wn * 32 + nt * 8 + t4 * 2;
            if (rbm < M)
                *(float2*)&C[(size_t)rbm * Nc + cc] =
                    make_float2(acc[mt][nt][0], acc[mt][nt][1]);
            if (rbm + 8 < M)
                *(float2*)&C[(size_t)(rbm + 8) * Nc + cc] =
                    make_float2(acc[mt][nt][2], acc[mt][nt][3]);
        }
    }

    // fused attention-logit partials: this block covers head = blockIdx.x
    {
        const int head = blockIdx.x;
        float ps[2][2] = {{0.f, 0.f}, {0.f, 0.f}};
        float pd[2][2] = {{0.f, 0.f}, {0.f, 0.f}};
#pragma unroll
        for (int nt = 0; nt < 4; nt++) {
#pragma unroll
            for (int j = 0; j < 2; j++) {
                int cl = wn * 32 + nt * 8 + t4 * 2 + j;   // col within head (0..63)
                float a_s = asrc[head * 64 + cl];
                float a_d = adst[head * 64 + cl];
#pragma unroll
                for (int mt = 0; mt < 2; mt++) {
                    ps[mt][0] += acc[mt][nt][j] * a_s;
                    pd[mt][0] += acc[mt][nt][j] * a_d;
                    ps[mt][1] += acc[mt][nt][2 + j] * a_s;
                    pd[mt][1] += acc[mt][nt][2 + j] * a_d;
                }
            }
        }
#pragma unroll
        for (int off = 1; off <= 2; off <<= 1) {
#pragma unroll
            for (int mt = 0; mt < 2; mt++)
#pragma unroll
                for (int hf = 0; hf < 2; hf++) {
                    ps[mt][hf] += __shfl_xor_sync(0xFFFFFFFFu, ps[mt][hf], off);
                    pd[mt][hf] += __shfl_xor_sync(0xFFFFFFFFu, pd[mt][hf], off);
                }
        }
        if (t4 == 0) {
#pragma unroll
            for (int mt = 0; mt < 2; mt++)
#pragma unroll
                for (int hf = 0; hf < 2; hf++) {
                    int row = row0 + wm * 32 + mt * 16 + g + hf * 8;
                    if (row < M) {
                        atomicAdd(&als[(size_t)row * Hn + head], ps[mt][hf]);
                        atomicAdd(&ald[(size_t)row * Hn + head], pd[mt][hf]);
                    }
                }
        }
    }
#undef GLDG
#undef GSTS
}

// ---------------- CSR build ------------------------------------------------
__global__ void zero_deg(int* __restrict__ deg, int N) {
    int i = blockIdx.x * blockDim.x + threadIdx.x;
    if (i < N) deg[i] = 0;
}
__global__ void build_deg(const int* __restrict__ dst, int* __restrict__ deg, int E) {
    int e = blockIdx.x * blockDim.x + threadIdx.x;
    if (e < E) atomicAdd(&deg[dst[e]], 1);
}
__global__ void scan_full(const int* __restrict__ deg, int* __restrict__ rowptr,
                          int* __restrict__ cursor, int n, int E) {
    __shared__ int wsum[32];
    __shared__ int carry;
    int lane = threadIdx.x & 31, wid = threadIdx.x >> 5;
    if (threadIdx.x == 0) carry = 0;
    __syncthreads();
    for (int base = 0; base < n; base += 1024) {
        int gid = base + threadIdx.x;
        int v = (gid < n) ? deg[gid] : 0;
        int x = v;
#pragma unroll
        for (int off = 1; off < 32; off <<= 1) {
            int y = __shfl_up_sync(0xFFFFFFFFu, x, off);
            if (lane >= off) x += y;
        }
        if (lane == 31) wsum[wid] = x;
        __syncthreads();
        if (wid == 0) {
            int w = wsum[lane];
#pragma unroll
            for (int off = 1; off < 32; off <<= 1) {
                int y = __shfl_up_sync(0xFFFFFFFFu, w, off);
                if (lane >= off) w += y;
            }
            wsum[lane] = w;
        }
        __syncthreads();
        int incl = x + ((wid > 0) ? wsum[wid - 1] : 0) + carry;
        if (gid < n) {
            rowptr[gid] = incl - v;
            cursor[gid] = incl - v;
        }
        __syncthreads();
        if (threadIdx.x == 1023) carry = incl;
        __syncthreads();
    }
    if (threadIdx.x == 0) rowptr[n] = E;
}
__global__ void scatter(const int* __restrict__ src, const int* __restrict__ dst,
                        int* __restrict__ cursor, int* __restrict__ csr_src, int E) {
    int e = blockIdx.x * blockDim.x + threadIdx.x;
    if (e >= E) return;
    int pos = atomicAdd(&cursor[dst[e]], 1);
    csr_src[pos] = src[e];
}

// ---------------- fused per-node GAT: online softmax + aggregate ------------
template <int H, int C, bool ELU, bool SPLITOUT>
__global__ void node_gat(const int* __restrict__ rowptr,
                         const int* __restrict__ csr_src,
                         const float* __restrict__ als,
                         const float* __restrict__ ald,
                         const float* __restrict__ h,
                         const float* __restrict__ bias,
                         float* __restrict__ out,
                         __nv_bfloat16* __restrict__ fhi,
                         __nv_bfloat16* __restrict__ flo, int N) {
    constexpr int F = H * C;
    int warp = (blockIdx.x * blockDim.x + threadIdx.x) >> 5;
    int lane = threadIdx.x & 31;
    if (warp >= N) return;
    const int d = warp;
    const int beg = rowptr[d], end = rowptr[d + 1];

    float aldv[H];
#pragma unroll
    for (int k = 0; k < H; k++) aldv[k] = ald[d * H + k];

    // single pass: online softmax (running max + rescaled sum), lane-strided
    float m[H], sum[H];
#pragma unroll
    for (int k = 0; k < H; k++) { m[k] = -3.402823466e38f; sum[k] = 0.0f; }
    for (int i = beg + lane; i < end; i += 32) {
        int s = csr_src[i];
#pragma unroll
        for (int k = 0; k < H; k++) {
            float v = als[s * H + k] + aldv[k];
            v = (v >= 0.0f) ? v : 0.2f * v;
            if (v <= m[k]) {
                sum[k] += __expf(v - m[k]);
            } else {
                sum[k] = sum[k] * __expf(m[k] - v) + 1.0f;
                m[k] = v;
            }
        }
    }
#pragma unroll
    for (int o = 16; o; o >>= 1) {
#pragma unroll
        for (int k = 0; k < H; k++) {
            float om = __shfl_xor_sync(0xFFFFFFFFu, m[k], o);
            float os = __shfl_xor_sync(0xFFFFFFFFu, sum[k], o);
            float nm = fmaxf(m[k], om);
            sum[k] = sum[k] * __expf(m[k] - nm) + os * __expf(om - nm);
            m[k] = nm;
        }
    }

    float inv[H];
#pragma unroll
    for (int k = 0; k < H; k++) inv[k] = 1.0f / (sum[k] + 1e-16f);

    if (F == 256) {
        float4 acc0 = make_float4(0.f, 0.f, 0.f, 0.f);
        float4 acc1 = make_float4(0.f, 0.f, 0.f, 0.f);
#pragma unroll 2
        for (int i = beg; i < end; i++) {
            int s = csr_src[i];
            float w[H];
#pragma unroll
            for (int k = 0; k < H; k++) {
                float v = als[s * H + k] + aldv[k];
                v = (v >= 0.0f) ? v : 0.2f * v;
                w[k] = __expf(v - m[k]) * inv[k];
            }
            const float4* hp = (const float4*)(h + (size_t)s * 256);
            float4 v0 = hp[lane];
            float4 v1 = hp[lane + 32];
            float a0 = w[lane >> 4];
            float a1 = w[2 + (lane >> 4)];
            acc0.x += a0 * v0.x; acc0.y += a0 * v0.y; acc0.z += a0 * v0.z; acc0.w += a0 * v0.w;
            acc1.x += a1 * v1.x; acc1.y += a1 * v1.y; acc1.z += a1 * v1.z; acc1.w += a1 * v1.w;
        }
        int c0 = lane * 4, c1 = 128 + lane * 4;
        float4 b0 = *(const float4*)&bias[c0];
        float4 b1 = *(const float4*)&bias[c1];
        float o0[4] = {acc0.x + b0.x, acc0.y + b0.y, acc0.z + b0.z, acc0.w + b0.w};
        float o1[4] = {acc1.x + b1.x, acc1.y + b1.y, acc1.z + b1.z, acc1.w + b1.w};
        if (ELU) {
#pragma unroll
            for (int j = 0; j < 4; j++) {
                o0[j] = (o0[j] > 0.f) ? o0[j] : expm1f(o0[j]);
                o1[j] = (o1[j] > 0.f) ? o1[j] : expm1f(o1[j]);
            }
        }
        if (SPLITOUT) {
            __nv_bfloat16 h4[4], l4[4];
#pragma unroll
            for (int j = 0; j < 4; j++) split_bf16(o0[j], h4[j], l4[j]);
            *(uint2*)&fhi[(size_t)d * 256 + c0] = *(uint2*)h4;
            *(uint2*)&flo[(size_t)d * 256 + c0] = *(uint2*)l4;
#pragma unroll
            for (int j = 0; j < 4; j++) split_bf16(o1[j], h4[j], l4[j]);
            *(uint2*)&fhi[(size_t)d * 256 + c1] = *(uint2*)h4;
            *(uint2*)&flo[(size_t)d * 256 + c1] = *(uint2*)l4;
        } else {
            *(float4*)&out[(size_t)d * 256 + c0] = make_float4(o0[0], o0[1], o0[2], o0[3]);
            *(float4*)&out[(size_t)d * 256 + c1] = make_float4(o1[0], o1[1], o1[2], o1[3]);
        }
    } else {  // F == 64, H == 1 (final layer, fp32 out)
        float2 acc = make_float2(0.f, 0.f);
#pragma unroll 2
        for (int i = beg; i < end; i++) {
            int s = csr_src[i];
            float v = als[s] + aldv[0];
            v = (v >= 0.0f) ? v : 0.2f * v;
            float w0 = __expf(v - m[0]) * inv[0];
            float2 vv = ((const float2*)(h + (size_t)s * 64))[lane];
            acc.x += w0 * vv.x;
            acc.y += w0 * vv.y;
        }
        int c = lane * 2;
        acc.x += bias[c];
        acc.y += bias[c + 1];
        if (ELU) {
            acc.x = (acc.x > 0.f) ? acc.x : expm1f(acc.x);
            acc.y = (acc.y > 0.f) ? acc.y : expm1f(acc.y);
        }
        *(float2*)&out[(size_t)d * 64 + c] = acc;
    }
}

// ---------------- launch ----------------------------------------------------
extern "C" void kernel_launch(void* const* d_in, const int* in_sizes, int n_in,
                              void* d_out, int out_size) {
    const float* x = (const float*)d_in[0];
    const int* ei = (const int*)d_in[1];   // int32 (JAX x64-disabled)
    const int N = in_sizes[0] / 128;
    const int E = in_sizes[1] / 2;
    const int* src = ei;
    const int* dst = ei + E;

    float *h, *als, *ald;
    __nv_bfloat16 *fhi, *flo, *wthi, *wtlo;
    int *csr_src, *deg, *rowptr, *cursor;
    cudaGetSymbolAddress((void**)&h,       g_h);
    cudaGetSymbolAddress((void**)&fhi,     g_feat_hi);
    cudaGetSymbolAddress((void**)&flo,     g_feat_lo);
    cudaGetSymbolAddress((void**)&wthi,    g_wt_hi);
    cudaGetSymbolAddress((void**)&wtlo,    g_wt_lo);
    cudaGetSymbolAddress((void**)&als,     g_als);
    cudaGetSymbolAddress((void**)&ald,     g_ald);
    cudaGetSymbolAddress((void**)&csr_src, g_csr_src);
    cudaGetSymbolAddress((void**)&deg,     g_deg);
    cudaGetSymbolAddress((void**)&rowptr,  g_rowptr);
    cudaGetSymbolAddress((void**)&cursor,  g_cursor);

    const float* W[4]   = {(const float*)d_in[3],  (const float*)d_in[7],
                           (const float*)d_in[11], (const float*)d_in[15]};
    const float* Asr[4] = {(const float*)d_in[4],  (const float*)d_in[8],
                           (const float*)d_in[12], (const float*)d_in[16]};
    const float* Ads[4] = {(const float*)d_in[5],  (const float*)d_in[9],
                           (const float*)d_in[13], (const float*)d_in[17]};
    const float* Bb[4]  = {(const float*)d_in[6],  (const float*)d_in[10],
                           (const float*)d_in[14], (const float*)d_in[18]};
    const int Ci[4] = {128, 256, 256, 256};
    const int Hh[4] = {4, 4, 4, 1};

    // Prologue ordered so launch index 3 is the layer-0 gemm (ncu samples it).
    wsplit<<<(Ci[0] * 256 + 255) / 256, 256>>>(W[0], wthi, wtlo, Ci[0], 256);     // 0
    splitx<<<(N * 32 + 255) / 256, 256>>>(x, fhi, flo, N * 32);                   // 1
    zal<<<(N * 4 + 255) / 256, 256>>>(als, ald, N * 4);                           // 2

    for (int l = 0; l < 4; l++) {
        const int H = Hh[l], F = H * 64, K = Ci[l];

        if (l > 0) zal<<<(N * H + 255) / 256, 256>>>(als, ald, N * H);

        dim3 ggrid(F / GBN, (N + GBM - 1) / GBM);
        gemm_bf16x3<<<ggrid, 256>>>(fhi, flo, wthi, wtlo, h, N, K, F,
                                    Asr[l], Ads[l], als, ald, H);                 // 3 (l=0)

        if (l == 0) {
            zero_deg<<<(N + 255) / 256, 256>>>(deg, N);
            build_deg<<<(E + 255) / 256, 256>>>(dst, deg, E);
            scan_full<<<1, 1024>>>(deg, rowptr, cursor, N, E);
            scatter<<<(E + 255) / 256, 256>>>(src, dst, cursor, csr_src, E);
        }

        int ngrid = (N * 32 + 255) / 256;
        if (l < 3) {
            node_gat<4, 64, true, true><<<ngrid, 256>>>(rowptr, csr_src, als, ald,
                                                        h, Bb[l], nullptr, fhi, flo, N);
            wsplit<<<(Ci[l + 1] * ((l + 1 < 3) ? 256 : 64) + 255) / 256, 256>>>(
                W[l + 1], wthi, wtlo, Ci[l + 1], (l + 1 < 3) ? 256 : 64);
        } else {
            node_gat<1, 64, false, false><<<ngrid, 256>>>(rowptr, csr_src, als, ald,
                                                          h, Bb[l], (float*)d_out,
                                                          nullptr, nullptr, N);
        }
    }
}